// round 6
// baseline (speedup 1.0000x reference)
#include <cuda_runtime.h>

#define T_LEN 1024
#define B_SZ  128
#define D_IN  32
#define H_DIM 64
#define W_DIM 128
#define C_DIM 33     // D_IN + 1
#define O_DIM 2112   // H_DIM * C_DIM
#define O_MAIN 2048  // main (uniform) part of layer-3 outputs

// Transposed copy of vW2 rows [0, 2048): g_vW2T[k * 2048 + o] = vW2[o * 128 + k]
__device__ float g_vW2T[W_DIM * O_MAIN];

__global__ void cde_transpose_kernel(const float* __restrict__ vW2) {
    int idx = blockIdx.x * blockDim.x + threadIdx.x;
    if (idx < W_DIM * O_MAIN) {
        int k = idx >> 11;     // / 2048
        int o = idx & 2047;
        g_vW2T[idx] = vW2[o * W_DIM + k];
    }
}

struct Smem {
    float vW0[W_DIM * 65];    // [j][i], stride 65 (odd -> conflict-free)
    float vW1[W_DIM * 129];   // [j][k], padded stride 129 (conflict-free)
    float vb0[W_DIM];
    float vb1[W_DIM];
    float vb2[O_DIM];
    float vbuf[2][O_DIM];     // v (tanh outputs), per batch
    float z1[2][W_DIM];
    float z2[2][W_DIM];
    float yhat1[2][H_DIM];
    float dxv[2][C_DIM];
    float cury[2][D_IN];
    float red[2][H_DIM];
};

__device__ __forceinline__ float lipswish_f(float x) {
    // 0.909 * x * sigmoid(x); handles +/- inf gracefully
    float sg = __fdividef(1.0f, 1.0f + __expf(-x));
    return 0.909f * x * sg;
}

__device__ __forceinline__ float tanh_f(float x) {
    // tanh(x) = 1 - 2/(e^{2x}+1); e->inf => 1, e->0 => -1
    float e = __expf(2.0f * x);
    return 1.0f - __fdividef(2.0f, e + 1.0f);
}

// Computes vbuf = tanh(vW2 @ lipswish(vW1 @ lipswish(vW0 @ [t, yhat1] + vb0) + vb1) + vb2)
// for both batches handled by this CTA. All 256 threads participate.
__device__ __forceinline__ void vf_eval(Smem* sm, int tid, float t1,
                                        const float* __restrict__ vW2) {
    const int bb = tid >> 7;
    const int j  = tid & 127;

    // ---- layer 1: (65 -> 128) ----
    {
        const float* w  = &sm->vW0[j * 65];
        const float* yh = sm->yhat1[bb];
        float a = sm->vb0[j] + t1 * w[0];
        #pragma unroll
        for (int i = 0; i < H_DIM; i++) a += yh[i] * w[i + 1];
        sm->z1[bb][j] = lipswish_f(a);
    }
    __syncthreads();

    // ---- layer 2: (128 -> 128) ----
    {
        const float* w = &sm->vW1[j * 129];
        const float* z = sm->z1[bb];
        float a = sm->vb1[j];
        #pragma unroll 16
        for (int k = 0; k < W_DIM; k++) a += z[k] * w[k];
        sm->z2[bb][j] = lipswish_f(a);
    }
    __syncthreads();

    // ---- layer 3 main: outputs [0, 2048), 8 per thread, both batches share each load ----
    {
        float a0[8], a1[8];
        #pragma unroll
        for (int i = 0; i < 8; i++) { a0[i] = 0.f; a1[i] = 0.f; }

        #pragma unroll 2
        for (int kk = 0; kk < 32; kk++) {
            float4 zq0 = *(const float4*)&sm->z2[0][4 * kk];
            float4 zq1 = *(const float4*)&sm->z2[1][4 * kk];
            float z0v[4] = {zq0.x, zq0.y, zq0.z, zq0.w};
            float z1v[4] = {zq1.x, zq1.y, zq1.z, zq1.w};
            #pragma unroll
            for (int u = 0; u < 4; u++) {
                const float* wrow = g_vW2T + (4 * kk + u) * O_MAIN;
                float4 wa = *(const float4*)(wrow + 4 * tid);
                float4 wb = *(const float4*)(wrow + 4 * tid + 1024);
                a0[0] += z0v[u] * wa.x;  a0[1] += z0v[u] * wa.y;
                a0[2] += z0v[u] * wa.z;  a0[3] += z0v[u] * wa.w;
                a0[4] += z0v[u] * wb.x;  a0[5] += z0v[u] * wb.y;
                a0[6] += z0v[u] * wb.z;  a0[7] += z0v[u] * wb.w;
                a1[0] += z1v[u] * wa.x;  a1[1] += z1v[u] * wa.y;
                a1[2] += z1v[u] * wa.z;  a1[3] += z1v[u] * wa.w;
                a1[4] += z1v[u] * wb.x;  a1[5] += z1v[u] * wb.y;
                a1[6] += z1v[u] * wb.z;  a1[7] += z1v[u] * wb.w;
            }
        }
        #pragma unroll
        for (int i = 0; i < 4; i++) {
            int o  = 4 * tid + i;
            float b = sm->vb2[o];
            sm->vbuf[0][o] = tanh_f(a0[i] + b);
            sm->vbuf[1][o] = tanh_f(a1[i] + b);
            int o2  = o + 1024;
            float b2 = sm->vb2[o2];
            sm->vbuf[0][o2] = tanh_f(a0[4 + i] + b2);
            sm->vbuf[1][o2] = tanh_f(a1[4 + i] + b2);
        }
    }

    // ---- layer 3 tail: outputs [2048, 2112), warp-per-output reduction over original vW2 ----
    {
        const int w = tid >> 5, lane = tid & 31;
        float4 zz0 = *(const float4*)&sm->z2[0][4 * lane];
        float4 zz1 = *(const float4*)&sm->z2[1][4 * lane];
        #pragma unroll
        for (int i = 0; i < 8; i++) {
            int o = O_MAIN + w * 8 + i;
            float4 wv = *(const float4*)(vW2 + (size_t)o * W_DIM + 4 * lane);
            float a0 = wv.x * zz0.x + wv.y * zz0.y + wv.z * zz0.z + wv.w * zz0.w;
            float a1 = wv.x * zz1.x + wv.y * zz1.y + wv.z * zz1.z + wv.w * zz1.w;
            #pragma unroll
            for (int off = 16; off; off >>= 1) {
                a0 += __shfl_xor_sync(0xffffffffu, a0, off);
                a1 += __shfl_xor_sync(0xffffffffu, a1, off);
            }
            if (lane == 0) {
                float b = sm->vb2[o];
                sm->vbuf[0][o] = tanh_f(a0 + b);
                sm->vbuf[1][o] = tanh_f(a1 + b);
            }
        }
    }
    __syncthreads();
}

__global__ void __launch_bounds__(256, 1) cde_kernel(
    const float* __restrict__ ts,  const float* __restrict__ ys,
    const float* __restrict__ iW0, const float* __restrict__ ib0,
    const float* __restrict__ iW1, const float* __restrict__ ib1,
    const float* __restrict__ iW2, const float* __restrict__ ib2,
    const float* __restrict__ vW0, const float* __restrict__ vb0,
    const float* __restrict__ vW1, const float* __restrict__ vb1,
    const float* __restrict__ vW2, const float* __restrict__ vb2,
    const float* __restrict__ rW,  const float* __restrict__ rb,
    float* __restrict__ out)
{
    extern __shared__ float smraw[];
    Smem* sm = reinterpret_cast<Smem*>(smraw);
    const int tid = threadIdx.x;
    const int b0  = blockIdx.x * 2;   // two batch elements per CTA

    // ---- stage weights into smem ----
    for (int i = tid; i < W_DIM * 65; i += 256) sm->vW0[i] = vW0[i];
    for (int i = tid; i < W_DIM * W_DIM; i += 256) {
        int j = i >> 7, k = i & 127;
        sm->vW1[j * 129 + k] = vW1[i];
    }
    if (tid < W_DIM) { sm->vb0[tid] = vb0[tid]; sm->vb1[tid] = vb1[tid]; }
    for (int i = tid; i < O_DIM; i += 256) sm->vb2[i] = vb2[i];

    // initial input x0 = [ts[0], ys[b,0,:]]  (reuse dxv buffer)
    if (tid < 66) {
        int bb = (tid < 33) ? 0 : 1;
        int c  = (tid < 33) ? tid : tid - 33;
        sm->dxv[bb][c] = (c == 0) ? ts[0]
                                  : ys[(size_t)(b0 + bb) * T_LEN * D_IN + (c - 1)];
    }
    if (tid < 64) {
        int bb = tid >> 5, c = tid & 31;
        sm->cury[bb][c] = ys[(size_t)(b0 + bb) * T_LEN * D_IN + c];
    }
    __syncthreads();

    // ---- initial MLP: relu(iW0 x + ib0) -> relu(iW1 . + ib1) -> iW2 . + ib2 ----
    {
        int bb = tid >> 7, j = tid & 127;
        float a = ib0[j];
        #pragma unroll
        for (int i = 0; i < C_DIM; i++) a += sm->dxv[bb][i] * iW0[j * C_DIM + i];
        sm->z1[bb][j] = fmaxf(a, 0.f);
    }
    __syncthreads();
    {
        int bb = tid >> 7, j = tid & 127;
        float a = ib1[j];
        #pragma unroll 8
        for (int k = 0; k < W_DIM; k++) a += sm->z1[bb][k] * iW1[j * W_DIM + k];
        sm->z2[bb][j] = fmaxf(a, 0.f);
    }
    __syncthreads();

    float y = 0.f, yhat = 0.f, sdot = 0.f;
    if (tid < 2 * H_DIM) {
        int bb = tid >> 6, h = tid & 63;
        float a = ib2[h];
        #pragma unroll 8
        for (int k = 0; k < W_DIM; k++) a += sm->z2[bb][k] * iW2[h * W_DIM + k];
        y = a; yhat = a;
        sm->yhat1[bb][h] = a;
    }
    __syncthreads();

    // v0 = vf(ts[0], y0)
    vf_eval(sm, tid, ts[0], vW2);

    // ---- scan over 1023 steps ----
    float tprev = ts[0];
    for (int t = 1; t < T_LEN; t++) {
        float t1 = __ldg(&ts[t]);

        // dx = x[t] - x[t-1]
        if (tid < 66) {
            int bb = (tid < 33) ? 0 : 1;
            int c  = (tid < 33) ? tid : tid - 33;
            if (c == 0) {
                sm->dxv[bb][0] = t1 - tprev;
            } else {
                float nv = ys[(size_t)(b0 + bb) * T_LEN * D_IN + (size_t)t * D_IN + (c - 1)];
                sm->dxv[bb][c] = nv - sm->cury[bb][c - 1];
                sm->cury[bb][c - 1] = nv;
            }
        }
        tprev = t1;
        __syncthreads();

        // s = v . dx ; yhat1 = 2y - yhat + s
        if (tid < 2 * H_DIM) {
            int bb = tid >> 6, h = tid & 63;
            const float* vp = &sm->vbuf[bb][h * C_DIM];
            const float* dp = sm->dxv[bb];
            float a = 0.f;
            #pragma unroll
            for (int c = 0; c < C_DIM; c++) a += vp[c] * dp[c];
            sdot = a;
            float yh1 = 2.f * y - yhat + a;
            yhat = yh1;
            sm->yhat1[bb][h] = yh1;
        }
        __syncthreads();

        // v1 = vf(t1, yhat1)  (overwrites vbuf)
        vf_eval(sm, tid, t1, vW2);

        // y += 0.5 * (s + v1 . dx)
        if (tid < 2 * H_DIM) {
            int bb = tid >> 6, h = tid & 63;
            const float* vp = &sm->vbuf[bb][h * C_DIM];
            const float* dp = sm->dxv[bb];
            float a = 0.f;
            #pragma unroll
            for (int c = 0; c < C_DIM; c++) a += vp[c] * dp[c];
            y += 0.5f * (sdot + a);
        }
        __syncthreads();   // protects dxv/cury for next iteration's writes
    }

    // ---- readout: out[b] = y . rW + rb ----
    if (tid < 2 * H_DIM) {
        int bb = tid >> 6, h = tid & 63;
        sm->red[bb][h] = y * rW[h];
    }
    __syncthreads();
    if (tid < 2) {
        float a = rb[0];
        #pragma unroll
        for (int h = 0; h < H_DIM; h++) a += sm->red[tid][h];
        out[b0 + tid] = a;
    }
}

extern "C" void kernel_launch(void* const* d_in, const int* in_sizes, int n_in,
                              void* d_out, int out_size) {
    (void)in_sizes; (void)n_in; (void)out_size;
    const float* ts  = (const float*)d_in[0];
    const float* ys  = (const float*)d_in[1];
    const float* iW0 = (const float*)d_in[2];
    const float* ib0 = (const float*)d_in[3];
    const float* iW1 = (const float*)d_in[4];
    const float* ib1 = (const float*)d_in[5];
    const float* iW2 = (const float*)d_in[6];
    const float* ib2 = (const float*)d_in[7];
    const float* vW0 = (const float*)d_in[8];
    const float* vb0 = (const float*)d_in[9];
    const float* vW1 = (const float*)d_in[10];
    const float* vb1 = (const float*)d_in[11];
    const float* vW2 = (const float*)d_in[12];
    const float* vb2 = (const float*)d_in[13];
    const float* rW  = (const float*)d_in[14];
    const float* rb  = (const float*)d_in[15];
    float* out = (float*)d_out;

    cudaFuncSetAttribute(cde_kernel, cudaFuncAttributeMaxDynamicSharedMemorySize,
                         (int)sizeof(Smem));

    cde_transpose_kernel<<<(W_DIM * O_MAIN + 255) / 256, 256>>>(vW2);
    cde_kernel<<<B_SZ / 2, 256, sizeof(Smem)>>>(
        ts, ys, iW0, ib0, iW1, ib1, iW2, ib2,
        vW0, vb0, vW1, vb1, vW2, vb2, rW, rb, out);
}

// round 7
// speedup vs baseline: 1.1886x; 1.1886x over previous
#include <cuda_runtime.h>

#define T_LEN 1024
#define B_SZ  128
#define D_IN  32
#define H_DIM 64
#define W_DIM 128
#define C_DIM 33     // D_IN + 1
#define O_DIM 2112   // H_DIM * C_DIM
#define O_MAIN 2048  // main (uniform) part of layer-3 outputs

// Transposed copy of vW2 rows [0, 2048): g_vW2T[k * 2048 + o] = vW2[o * 128 + k]
__device__ float g_vW2T[W_DIM * O_MAIN];

__global__ void cde_transpose_kernel(const float* __restrict__ vW2) {
    int idx = blockIdx.x * blockDim.x + threadIdx.x;
    if (idx < W_DIM * O_MAIN) {
        int k = idx >> 11;     // / 2048
        int o = idx & 2047;
        g_vW2T[idx] = vW2[o * W_DIM + k];
    }
}

struct __align__(16) Smem {
    float vW0p[W_DIM * 66];   // [j][pairable w[1..64]]; stride 66 = 2*33 -> LDS.64 conflict-free
    float vW0c[W_DIM];        // w[j][0] (the t column)
    float vW1[W_DIM * 130];   // [j][k], stride 130 = 2*65 -> LDS.64 conflict-free
    float vb0[W_DIM];
    float vb1[W_DIM];
    float vb2[O_DIM];
    float vbuf[2][O_DIM];     // v (tanh outputs), per batch
    float z1[2][W_DIM];
    float z2[2][W_DIM];
    float yhat1[2][H_DIM];
    float dxv[2][C_DIM];
    float cury[2][D_IN];
    float red[2][H_DIM];
};

typedef unsigned long long u64;

__device__ __forceinline__ void ffma2(u64& d, u64 a, u64 b) {
    // d.lo += a.lo*b.lo ; d.hi += a.hi*b.hi  (packed fp32x2 FMA, sm_100+)
    asm("fma.rn.f32x2 %0, %1, %2, %0;" : "+l"(d) : "l"(a), "l"(b));
}
__device__ __forceinline__ u64 pack2(float x, float y) {
    u64 r;
    asm("mov.b64 %0, {%1, %2};" : "=l"(r) : "f"(x), "f"(y));
    return r;
}
__device__ __forceinline__ float2 unpack2(u64 v) {
    float2 r;
    asm("mov.b64 {%0, %1}, %2;" : "=f"(r.x), "=f"(r.y) : "l"(v));
    return r;
}

__device__ __forceinline__ float lipswish_f(float x) {
    float sg = __fdividef(1.0f, 1.0f + __expf(-x));
    return 0.909f * x * sg;
}

__device__ __forceinline__ float tanh_f(float x) {
    float e = __expf(2.0f * x);
    return 1.0f - __fdividef(2.0f, e + 1.0f);
}

// vbuf = tanh(vW2 @ lipswish(vW1 @ lipswish(vW0 @ [t, yhat1] + vb0) + vb1) + vb2)
// for both batches handled by this CTA. All 256 threads participate.
__device__ __forceinline__ void vf_eval(Smem* sm, int tid, float t1,
                                        const float* __restrict__ vW2) {
    const int bb = tid >> 7;
    const int j  = tid & 127;

    // ---- layer 1: (65 -> 128), paired FFMA2 over the 64 yh inputs ----
    {
        const u64* wp = (const u64*)&sm->vW0p[j * 66];
        const u64* yp = (const u64*)sm->yhat1[bb];
        u64 acc[4] = {0ull, 0ull, 0ull, 0ull};
        #pragma unroll
        for (int p = 0; p < 32; p++) ffma2(acc[p & 3], wp[p], yp[p]);
        float2 s0 = unpack2(acc[0]), s1 = unpack2(acc[1]);
        float2 s2 = unpack2(acc[2]), s3 = unpack2(acc[3]);
        float a = sm->vb0[j] + t1 * sm->vW0c[j]
                + ((s0.x + s0.y) + (s1.x + s1.y))
                + ((s2.x + s2.y) + (s3.x + s3.y));
        sm->z1[bb][j] = lipswish_f(a);
    }
    __syncthreads();

    // ---- layer 2: (128 -> 128), paired ----
    {
        const u64* wp = (const u64*)&sm->vW1[j * 130];
        const u64* zp = (const u64*)sm->z1[bb];
        u64 acc[4] = {0ull, 0ull, 0ull, 0ull};
        #pragma unroll
        for (int p = 0; p < 64; p++) ffma2(acc[p & 3], wp[p], zp[p]);
        float2 s0 = unpack2(acc[0]), s1 = unpack2(acc[1]);
        float2 s2 = unpack2(acc[2]), s3 = unpack2(acc[3]);
        float a = sm->vb1[j]
                + ((s0.x + s0.y) + (s1.x + s1.y))
                + ((s2.x + s2.y) + (s3.x + s3.y));
        sm->z2[bb][j] = lipswish_f(a);
    }
    __syncthreads();

    // ---- layer 3 main: outputs [0, 2048), 8 per thread x 2 batches.
    // Weight pairs come straight from the LDG.128 (no packing); only z needs a dup.
    {
        u64 acc[8];   // [b0: wa01, wa23, wb01, wb23 | b1: same]
        #pragma unroll
        for (int i = 0; i < 8; i++) acc[i] = 0ull;

        #pragma unroll 4
        for (int kk = 0; kk < 32; kk++) {
            float4 zq0 = *(const float4*)&sm->z2[0][4 * kk];   // broadcast LDS
            float4 zq1 = *(const float4*)&sm->z2[1][4 * kk];
            const float z0v[4] = {zq0.x, zq0.y, zq0.z, zq0.w};
            const float z1v[4] = {zq1.x, zq1.y, zq1.z, zq1.w};
            #pragma unroll
            for (int u = 0; u < 4; u++) {
                const float* wrow = g_vW2T + (4 * kk + u) * O_MAIN;
                ulonglong2 wa = *(const ulonglong2*)(wrow + 4 * tid);
                ulonglong2 wb = *(const ulonglong2*)(wrow + 4 * tid + 1024);
                u64 zz0 = pack2(z0v[u], z0v[u]);
                u64 zz1 = pack2(z1v[u], z1v[u]);
                ffma2(acc[0], wa.x, zz0); ffma2(acc[1], wa.y, zz0);
                ffma2(acc[2], wb.x, zz0); ffma2(acc[3], wb.y, zz0);
                ffma2(acc[4], wa.x, zz1); ffma2(acc[5], wa.y, zz1);
                ffma2(acc[6], wb.x, zz1); ffma2(acc[7], wb.y, zz1);
            }
        }
        // epilogue: bias + tanh + store
        {
            int oa = 4 * tid, ob = 4 * tid + 1024;
            float2 r;
            r = unpack2(acc[0]);
            sm->vbuf[0][oa + 0] = tanh_f(r.x + sm->vb2[oa + 0]);
            sm->vbuf[0][oa + 1] = tanh_f(r.y + sm->vb2[oa + 1]);
            r = unpack2(acc[1]);
            sm->vbuf[0][oa + 2] = tanh_f(r.x + sm->vb2[oa + 2]);
            sm->vbuf[0][oa + 3] = tanh_f(r.y + sm->vb2[oa + 3]);
            r = unpack2(acc[2]);
            sm->vbuf[0][ob + 0] = tanh_f(r.x + sm->vb2[ob + 0]);
            sm->vbuf[0][ob + 1] = tanh_f(r.y + sm->vb2[ob + 1]);
            r = unpack2(acc[3]);
            sm->vbuf[0][ob + 2] = tanh_f(r.x + sm->vb2[ob + 2]);
            sm->vbuf[0][ob + 3] = tanh_f(r.y + sm->vb2[ob + 3]);
            r = unpack2(acc[4]);
            sm->vbuf[1][oa + 0] = tanh_f(r.x + sm->vb2[oa + 0]);
            sm->vbuf[1][oa + 1] = tanh_f(r.y + sm->vb2[oa + 1]);
            r = unpack2(acc[5]);
            sm->vbuf[1][oa + 2] = tanh_f(r.x + sm->vb2[oa + 2]);
            sm->vbuf[1][oa + 3] = tanh_f(r.y + sm->vb2[oa + 3]);
            r = unpack2(acc[6]);
            sm->vbuf[1][ob + 0] = tanh_f(r.x + sm->vb2[ob + 0]);
            sm->vbuf[1][ob + 1] = tanh_f(r.y + sm->vb2[ob + 1]);
            r = unpack2(acc[7]);
            sm->vbuf[1][ob + 2] = tanh_f(r.x + sm->vb2[ob + 2]);
            sm->vbuf[1][ob + 3] = tanh_f(r.y + sm->vb2[ob + 3]);
        }
    }

    // ---- layer 3 tail: outputs [2048, 2112), warp-per-output reduction over original vW2 ----
    {
        const int w = tid >> 5, lane = tid & 31;
        float4 zz0 = *(const float4*)&sm->z2[0][4 * lane];
        float4 zz1 = *(const float4*)&sm->z2[1][4 * lane];
        #pragma unroll
        for (int i = 0; i < 8; i++) {
            int o = O_MAIN + w * 8 + i;
            float4 wv = *(const float4*)(vW2 + (size_t)o * W_DIM + 4 * lane);
            float a0 = wv.x * zz0.x + wv.y * zz0.y + wv.z * zz0.z + wv.w * zz0.w;
            float a1 = wv.x * zz1.x + wv.y * zz1.y + wv.z * zz1.z + wv.w * zz1.w;
            #pragma unroll
            for (int off = 16; off; off >>= 1) {
                a0 += __shfl_xor_sync(0xffffffffu, a0, off);
                a1 += __shfl_xor_sync(0xffffffffu, a1, off);
            }
            if (lane == 0) {
                float b = sm->vb2[o];
                sm->vbuf[0][o] = tanh_f(a0 + b);
                sm->vbuf[1][o] = tanh_f(a1 + b);
            }
        }
    }
    __syncthreads();
}

__global__ void __launch_bounds__(256, 1) cde_kernel(
    const float* __restrict__ ts,  const float* __restrict__ ys,
    const float* __restrict__ iW0, const float* __restrict__ ib0,
    const float* __restrict__ iW1, const float* __restrict__ ib1,
    const float* __restrict__ iW2, const float* __restrict__ ib2,
    const float* __restrict__ vW0, const float* __restrict__ vb0,
    const float* __restrict__ vW1, const float* __restrict__ vb1,
    const float* __restrict__ vW2, const float* __restrict__ vb2,
    const float* __restrict__ rW,  const float* __restrict__ rb,
    float* __restrict__ out)
{
    extern __shared__ float smraw[];
    Smem* sm = reinterpret_cast<Smem*>(smraw);
    const int tid = threadIdx.x;
    const int b0  = blockIdx.x * 2;   // two batch elements per CTA

    // ---- stage weights into smem (paired layouts) ----
    for (int i = tid; i < W_DIM * 65; i += 256) {
        int j = i / 65, c = i % 65;
        if (c == 0) sm->vW0c[j] = vW0[i];
        else        sm->vW0p[j * 66 + (c - 1)] = vW0[i];
    }
    for (int i = tid; i < W_DIM * W_DIM; i += 256) {
        int j = i >> 7, k = i & 127;
        sm->vW1[j * 130 + k] = vW1[i];
    }
    if (tid < W_DIM) { sm->vb0[tid] = vb0[tid]; sm->vb1[tid] = vb1[tid]; }
    for (int i = tid; i < O_DIM; i += 256) sm->vb2[i] = vb2[i];

    // initial input x0 = [ts[0], ys[b,0,:]]  (reuse dxv buffer)
    if (tid < 66) {
        int bb = (tid < 33) ? 0 : 1;
        int c  = (tid < 33) ? tid : tid - 33;
        sm->dxv[bb][c] = (c == 0) ? ts[0]
                                  : ys[(size_t)(b0 + bb) * T_LEN * D_IN + (c - 1)];
    }
    if (tid < 64) {
        int bb = tid >> 5, c = tid & 31;
        sm->cury[bb][c] = ys[(size_t)(b0 + bb) * T_LEN * D_IN + c];
    }
    __syncthreads();

    // ---- initial MLP: relu(iW0 x + ib0) -> relu(iW1 . + ib1) -> iW2 . + ib2 ----
    {
        int bb = tid >> 7, j = tid & 127;
        float a = ib0[j];
        #pragma unroll
        for (int i = 0; i < C_DIM; i++) a += sm->dxv[bb][i] * iW0[j * C_DIM + i];
        sm->z1[bb][j] = fmaxf(a, 0.f);
    }
    __syncthreads();
    {
        int bb = tid >> 7, j = tid & 127;
        float a = ib1[j];
        #pragma unroll 8
        for (int k = 0; k < W_DIM; k++) a += sm->z1[bb][k] * iW1[j * W_DIM + k];
        sm->z2[bb][j] = fmaxf(a, 0.f);
    }
    __syncthreads();

    float y = 0.f, yhat = 0.f, sdot = 0.f;
    if (tid < 2 * H_DIM) {
        int bb = tid >> 6, h = tid & 63;
        float a = ib2[h];
        #pragma unroll 8
        for (int k = 0; k < W_DIM; k++) a += sm->z2[bb][k] * iW2[h * W_DIM + k];
        y = a; yhat = a;
        sm->yhat1[bb][h] = a;
    }
    __syncthreads();

    // v0 = vf(ts[0], y0)
    vf_eval(sm, tid, ts[0], vW2);

    // ---- scan over 1023 steps ----
    float tprev = ts[0];
    for (int t = 1; t < T_LEN; t++) {
        float t1 = __ldg(&ts[t]);

        // dx = x[t] - x[t-1]
        if (tid < 66) {
            int bb = (tid < 33) ? 0 : 1;
            int c  = (tid < 33) ? tid : tid - 33;
            if (c == 0) {
                sm->dxv[bb][0] = t1 - tprev;
            } else {
                float nv = ys[(size_t)(b0 + bb) * T_LEN * D_IN + (size_t)t * D_IN + (c - 1)];
                sm->dxv[bb][c] = nv - sm->cury[bb][c - 1];
                sm->cury[bb][c - 1] = nv;
            }
        }
        tprev = t1;
        __syncthreads();

        // s = v . dx ; yhat1 = 2y - yhat + s
        if (tid < 2 * H_DIM) {
            int bb = tid >> 6, h = tid & 63;
            const float* vp = &sm->vbuf[bb][h * C_DIM];
            const float* dp = sm->dxv[bb];
            float a = 0.f;
            #pragma unroll
            for (int c = 0; c < C_DIM; c++) a += vp[c] * dp[c];
            sdot = a;
            float yh1 = 2.f * y - yhat + a;
            yhat = yh1;
            sm->yhat1[bb][h] = yh1;
        }
        __syncthreads();

        // v1 = vf(t1, yhat1)  (overwrites vbuf)
        vf_eval(sm, tid, t1, vW2);

        // y += 0.5 * (s + v1 . dx)
        if (tid < 2 * H_DIM) {
            int bb = tid >> 6, h = tid & 63;
            const float* vp = &sm->vbuf[bb][h * C_DIM];
            const float* dp = sm->dxv[bb];
            float a = 0.f;
            #pragma unroll
            for (int c = 0; c < C_DIM; c++) a += vp[c] * dp[c];
            y += 0.5f * (sdot + a);
        }
        __syncthreads();   // protects dxv/cury for next iteration's writes
    }

    // ---- readout: out[b] = y . rW + rb ----
    if (tid < 2 * H_DIM) {
        int bb = tid >> 6, h = tid & 63;
        sm->red[bb][h] = y * rW[h];
    }
    __syncthreads();
    if (tid < 2) {
        float a = rb[0];
        #pragma unroll
        for (int h = 0; h < H_DIM; h++) a += sm->red[tid][h];
        out[b0 + tid] = a;
    }
}

extern "C" void kernel_launch(void* const* d_in, const int* in_sizes, int n_in,
                              void* d_out, int out_size) {
    (void)in_sizes; (void)n_in; (void)out_size;
    const float* ts  = (const float*)d_in[0];
    const float* ys  = (const float*)d_in[1];
    const float* iW0 = (const float*)d_in[2];
    const float* ib0 = (const float*)d_in[3];
    const float* iW1 = (const float*)d_in[4];
    const float* ib1 = (const float*)d_in[5];
    const float* iW2 = (const float*)d_in[6];
    const float* ib2 = (const float*)d_in[7];
    const float* vW0 = (const float*)d_in[8];
    const float* vb0 = (const float*)d_in[9];
    const float* vW1 = (const float*)d_in[10];
    const float* vb1 = (const float*)d_in[11];
    const float* vW2 = (const float*)d_in[12];
    const float* vb2 = (const float*)d_in[13];
    const float* rW  = (const float*)d_in[14];
    const float* rb  = (const float*)d_in[15];
    float* out = (float*)d_out;

    cudaFuncSetAttribute(cde_kernel, cudaFuncAttributeMaxDynamicSharedMemorySize,
                         (int)sizeof(Smem));

    cde_transpose_kernel<<<(W_DIM * O_MAIN + 255) / 256, 256>>>(vW2);
    cde_kernel<<<B_SZ / 2, 256, sizeof(Smem)>>>(
        ts, ys, iW0, ib0, iW1, ib1, iW2, ib2,
        vW0, vb0, vW1, vb1, vW2, vb2, rW, rb, out);
}